// round 12
// baseline (speedup 1.0000x reference)
#include <cuda_runtime.h>
#include <cstdint>
#include <math.h>
#include <float.h>

#define NMAX 50000
#define EMAX 800000
#define ETMAX (NMAX + EMAX)
#define HID 128
#define NHEAD 16

// ---------------- device scratch (no allocations allowed) ----------------
__device__ __align__(16) float g_xh[(size_t)NMAX * HID];   // per-layer transformed features
__device__ __align__(16) float g_h [(size_t)NMAX * HID];   // layer-1 output (post ELU)
__device__ float g_als[NMAX * NHEAD];
__device__ float g_ald[NMAX * NHEAD];
__device__ int   g_deg[NMAX + 1];
__device__ int   g_off[NMAX + 1];    // read-only after scan
__device__ int   g_pos[NMAX];        // scatter cursor (init = off, consumed by atomics)
__device__ int   g_csr[ETMAX];       // src node ids grouped by dst
__device__ int   g_is64;             // edge_index element width flag

// ---------------- async copy helpers (LDGSTS) ----------------
__device__ __forceinline__ void cp_async16(void* smem_dst, const void* gmem_src) {
    uint32_t d = (uint32_t)__cvta_generic_to_shared(smem_dst);
    asm volatile("cp.async.cg.shared.global [%0], [%1], 16;" :: "r"(d), "l"(gmem_src));
}
__device__ __forceinline__ void cp_async_wait_all() {
    asm volatile("cp.async.commit_group;");
    asm volatile("cp.async.wait_group 0;");
}

// ---------------- online-softmax update helper ----------------
// Exactly one of exp(m-mn), exp(e-mn) is exp(0)=1 since mn=max(m,e).
// Compute the non-trivial one with a single MUFU: q = exp(-|e-m|).
__device__ __forceinline__ void online_upd(float& m, float& d, float4& acc,
                                           float e, const float4& xv) {
    float q = __expf(-fabsf(e - m));
    bool up = e > m;                 // new max
    float sc = up ? q : 1.f;
    float p  = up ? 1.f : q;
    m = fmaxf(m, e);
    d = d * sc + p;
    acc.x = acc.x * sc + p * xv.x;
    acc.y = acc.y * sc + p * xv.y;
    acc.z = acc.z * sc + p * xv.z;
    acc.w = acc.w * sc + p * xv.w;
}

// ---------------- CSR init + edge_index dtype detection (fused) ----------------
// jnp.int64 under default JAX config silently becomes int32; detect which one
// we actually got. If data is int64 (values < 2^31, nonneg), every odd 32-bit
// word is zero. If int32, odd words are random node ids in [0, 50000).
__global__ void k_init(const unsigned* __restrict__ w, int N) {
    int i = blockIdx.x * blockDim.x + threadIdx.x;
    if (i <= N) g_deg[i] = 0;
    if (blockIdx.x == 0) {
        __shared__ int any;
        if (threadIdx.x == 0) any = 0;
        __syncthreads();
        if (w[threadIdx.x * 2 + 1] != 0u) atomicOr(&any, 1);
        __syncthreads();
        if (threadIdx.x == 0) g_is64 = (any == 0) ? 1 : 0;
    }
}

__device__ __forceinline__ int load_ei_w(const void* p, long long idx, int is64) {
    return is64 ? (int)((const long long*)p)[idx] : ((const int*)p)[idx];
}

__global__ void k_count(const void* __restrict__ ei, int E, int N) {
    int e = blockIdx.x * blockDim.x + threadIdx.x;
    int ET = E + N;
    if (e >= ET) return;
    int is64 = g_is64;   // hoisted once
    int dst = (e < E) ? load_ei_w(ei, (long long)E + e, is64) : (e - E);
    atomicAdd(&g_deg[dst], 1);
}

// single-block exclusive scan of g_deg[0..N] -> g_off[0..N] and g_pos[0..N-1]
__global__ void k_scan(int N) {
    __shared__ int sh[1024];
    int t = threadIdx.x;
    int M = N + 1;
    int chunk = (M + 1023) >> 10;
    int start = t * chunk;
    int end = min(start + chunk, M);
    int sum = 0;
    for (int i = start; i < end; i++) sum += g_deg[i];
    sh[t] = sum;
    __syncthreads();
    for (int o = 1; o < 1024; o <<= 1) {
        int v = (t >= o) ? sh[t - o] : 0;
        __syncthreads();
        sh[t] += v;
        __syncthreads();
    }
    int run = (t > 0) ? sh[t - 1] : 0;
    for (int i = start; i < end; i++) {
        g_off[i] = run;
        if (i < N) g_pos[i] = run;   // scatter cursor starts at the offset
        run += g_deg[i];
    }
}

__global__ void k_scatter(const void* __restrict__ ei, int E, int N) {
    int e = blockIdx.x * blockDim.x + threadIdx.x;
    int ET = E + N;
    if (e >= ET) return;
    int is64 = g_is64;   // hoisted once
    int src, dst;
    if (e < E) { src = load_ei_w(ei, e, is64); dst = load_ei_w(ei, (long long)E + e, is64); }
    else       { src = e - E;                  dst = e - E; }
    int pos = atomicAdd(&g_pos[dst], 1);   // atomic return IS the slot
    g_csr[pos] = src;
}

// ---------------- fused GEMM + attention logits ----------------
// xh = X @ W  (N x 128 @ 128 x 128), plus per-(node,head) dots with a_src/a_dst.
// Block tile: 64 rows x 128 cols. 256 threads: cg = tid&31 (4-col group),
// rg = tid>>5 (8-row group). W fully staged in smem (64KB) + X tile (32KB)
// via cp.async. 2 blocks/SM -> 4 warps/SMSP to hide LDS latency.
__global__ void __launch_bounds__(256)
k_gemm(const float4* __restrict__ X, const float* __restrict__ W,
       const float* __restrict__ a_s, const float* __restrict__ a_d,
       float4* __restrict__ XH, float* __restrict__ ALS,
       float* __restrict__ ALD, int N) {
    extern __shared__ float sm[];
    float* Ws = sm;                  // 16384 floats
    float* Xs = sm + 16384;          // 8192 floats
    float* sA = sm + 16384 + 8192;   // 128
    float* sD = sA + 128;            // 128

    int tid = threadIdx.x;
    int cg = tid & 31, rg = tid >> 5;
    int rb = blockIdx.x * 64;

    const float4* W4 = (const float4*)W;
    float4* Ws4 = (float4*)Ws;
    float4* Xs4 = (float4*)Xs;

#pragma unroll
    for (int i = 0; i < 16; i++)
        cp_async16(&Ws4[tid + i * 256], &W4[tid + i * 256]);

    if (rb + 64 <= N) {
#pragma unroll
        for (int i = 0; i < 8; i++) {
            int idx = tid + i * 256;           // 0..2047
            int r = idx >> 5, c = idx & 31;
            cp_async16(&Xs4[idx], &X[(size_t)(rb + r) * 32 + c]);
        }
    } else {
#pragma unroll
        for (int i = 0; i < 8; i++) {
            int idx = tid + i * 256;
            int r = idx >> 5, c = idx & 31;
            float4 v = make_float4(0.f, 0.f, 0.f, 0.f);
            if (rb + r < N) v = X[(size_t)(rb + r) * 32 + c];
            Xs4[idx] = v;
        }
    }
    if (tid < 128) { sA[tid] = a_s[tid]; sD[tid] = a_d[tid]; }
    cp_async_wait_all();
    __syncthreads();

    float4 acc[8];
#pragma unroll
    for (int i = 0; i < 8; i++) acc[i] = make_float4(0.f, 0.f, 0.f, 0.f);

    const float4* Wsv = (const float4*)Ws;
    const float4* Xsv = (const float4*)Xs;   // 32 float4 per 128-col row
#pragma unroll 2
    for (int k4 = 0; k4 < 32; k4++) {
        float4 w0 = Wsv[(4 * k4 + 0) * 32 + cg];
        float4 w1 = Wsv[(4 * k4 + 1) * 32 + cg];
        float4 w2 = Wsv[(4 * k4 + 2) * 32 + cg];
        float4 w3 = Wsv[(4 * k4 + 3) * 32 + cg];
#pragma unroll
        for (int i = 0; i < 8; i++) {
            float4 xv = Xsv[((rg << 3) + i) * 32 + k4];   // warp-uniform broadcast
            acc[i].x += xv.x * w0.x + xv.y * w1.x + xv.z * w2.x + xv.w * w3.x;
            acc[i].y += xv.x * w0.y + xv.y * w1.y + xv.z * w2.y + xv.w * w3.y;
            acc[i].z += xv.x * w0.z + xv.y * w1.z + xv.z * w2.z + xv.w * w3.z;
            acc[i].w += xv.x * w0.w + xv.y * w1.w + xv.z * w2.w + xv.w * w3.w;
        }
    }

    float a0 = sA[4 * cg], a1 = sA[4 * cg + 1], a2 = sA[4 * cg + 2], a3 = sA[4 * cg + 3];
    float d0 = sD[4 * cg], d1 = sD[4 * cg + 1], d2 = sD[4 * cg + 2], d3 = sD[4 * cg + 3];
    int h = cg >> 1;  // cols 4cg..4cg+3 all belong to head cg/2
#pragma unroll
    for (int i = 0; i < 8; i++) {
        int row = rb + (rg << 3) + i;               // uniform across warp
        float ps = acc[i].x * a0 + acc[i].y * a1 + acc[i].z * a2 + acc[i].w * a3;
        float pd = acc[i].x * d0 + acc[i].y * d1 + acc[i].z * d2 + acc[i].w * d3;
        ps += __shfl_xor_sync(0xffffffffu, ps, 1);  // combine the two half-heads
        pd += __shfl_xor_sync(0xffffffffu, pd, 1);
        if (row < N) {
            XH[(size_t)row * 32 + cg] = acc[i];
            if (!(cg & 1)) {
                ALS[row * NHEAD + h] = ps;
                ALD[row * NHEAD + h] = pd;
            }
        }
    }
}

// ---------------- single-pass online softmax + aggregation (warp per dst) ----------------
// Flash-attention style: one pass over edges; acc and denom rescaled online.
// Exact (one of the two exps is exp(0)=1 so a single MUFU per edge suffices).
// Lane l owns cols 4l..4l+3 => head l/2. 8-edge batches with the NEXT batch's
// csr indices prefetched before the update chain. 512-thread blocks (16
// independent warps, no block sync) to halve CTA count.
__global__ void __launch_bounds__(512)
k_agg(const float4* __restrict__ XH, const float* __restrict__ ALS,
      const float* __restrict__ ALD, const float* __restrict__ bias,
      float4* __restrict__ OUT, int N, int do_elu) {
    int n = (blockIdx.x * blockDim.x + threadIdx.x) >> 5;
    int l = threadIdx.x & 31;
    if (n >= N) return;

    int base = g_off[n];
    int deg = g_off[n + 1] - base;

    unsigned hl = (unsigned)(l >> 1);
    float ac = ALD[(unsigned)n * NHEAD + hl];   // lane pairs: broadcast load

    float m = -FLT_MAX, d = 0.f;
    float4 acc = make_float4(0.f, 0.f, 0.f, 0.f);

    int nb = deg >> 3;               // full 8-edge batches
    int j = nb << 3;                 // remainder start
    if (nb > 0) {
        unsigned s0, s1, s2, s3, s4, s5, s6, s7;
        s0 = (unsigned)__ldg(&g_csr[base + 0]);
        s1 = (unsigned)__ldg(&g_csr[base + 1]);
        s2 = (unsigned)__ldg(&g_csr[base + 2]);
        s3 = (unsigned)__ldg(&g_csr[base + 3]);
        s4 = (unsigned)__ldg(&g_csr[base + 4]);
        s5 = (unsigned)__ldg(&g_csr[base + 5]);
        s6 = (unsigned)__ldg(&g_csr[base + 6]);
        s7 = (unsigned)__ldg(&g_csr[base + 7]);
        for (int b = 0; b < nb; b++) {
            // dependent gathers for the current batch
            float e0 = ALS[s0 * NHEAD + hl] + ac;
            float e1 = ALS[s1 * NHEAD + hl] + ac;
            float e2 = ALS[s2 * NHEAD + hl] + ac;
            float e3 = ALS[s3 * NHEAD + hl] + ac;
            float e4 = ALS[s4 * NHEAD + hl] + ac;
            float e5 = ALS[s5 * NHEAD + hl] + ac;
            float e6 = ALS[s6 * NHEAD + hl] + ac;
            float e7 = ALS[s7 * NHEAD + hl] + ac;
            float4 x0 = XH[s0 * 32u + (unsigned)l];
            float4 x1 = XH[s1 * 32u + (unsigned)l];
            float4 x2 = XH[s2 * 32u + (unsigned)l];
            float4 x3 = XH[s3 * 32u + (unsigned)l];
            float4 x4 = XH[s4 * 32u + (unsigned)l];
            float4 x5 = XH[s5 * 32u + (unsigned)l];
            float4 x6 = XH[s6 * 32u + (unsigned)l];
            float4 x7 = XH[s7 * 32u + (unsigned)l];
            // prefetch next batch's indices (overlaps the update chain below)
            if (b + 1 < nb) {
                int nxt = base + ((b + 1) << 3);
                s0 = (unsigned)__ldg(&g_csr[nxt + 0]);
                s1 = (unsigned)__ldg(&g_csr[nxt + 1]);
                s2 = (unsigned)__ldg(&g_csr[nxt + 2]);
                s3 = (unsigned)__ldg(&g_csr[nxt + 3]);
                s4 = (unsigned)__ldg(&g_csr[nxt + 4]);
                s5 = (unsigned)__ldg(&g_csr[nxt + 5]);
                s6 = (unsigned)__ldg(&g_csr[nxt + 6]);
                s7 = (unsigned)__ldg(&g_csr[nxt + 7]);
            }
            e0 = e0 > 0.f ? e0 : 0.2f * e0;
            e1 = e1 > 0.f ? e1 : 0.2f * e1;
            e2 = e2 > 0.f ? e2 : 0.2f * e2;
            e3 = e3 > 0.f ? e3 : 0.2f * e3;
            e4 = e4 > 0.f ? e4 : 0.2f * e4;
            e5 = e5 > 0.f ? e5 : 0.2f * e5;
            e6 = e6 > 0.f ? e6 : 0.2f * e6;
            e7 = e7 > 0.f ? e7 : 0.2f * e7;

            online_upd(m, d, acc, e0, x0);
            online_upd(m, d, acc, e1, x1);
            online_upd(m, d, acc, e2, x2);
            online_upd(m, d, acc, e3, x3);
            online_upd(m, d, acc, e4, x4);
            online_upd(m, d, acc, e5, x5);
            online_upd(m, d, acc, e6, x6);
            online_upd(m, d, acc, e7, x7);
        }
    }
    for (; j + 4 <= deg; j += 4) {
        unsigned s0 = (unsigned)__ldg(&g_csr[base + j]);
        unsigned s1 = (unsigned)__ldg(&g_csr[base + j + 1]);
        unsigned s2 = (unsigned)__ldg(&g_csr[base + j + 2]);
        unsigned s3 = (unsigned)__ldg(&g_csr[base + j + 3]);
        float e0 = ALS[s0 * NHEAD + hl] + ac;
        float e1 = ALS[s1 * NHEAD + hl] + ac;
        float e2 = ALS[s2 * NHEAD + hl] + ac;
        float e3 = ALS[s3 * NHEAD + hl] + ac;
        float4 x0 = XH[s0 * 32u + (unsigned)l];
        float4 x1 = XH[s1 * 32u + (unsigned)l];
        float4 x2 = XH[s2 * 32u + (unsigned)l];
        float4 x3 = XH[s3 * 32u + (unsigned)l];
        e0 = e0 > 0.f ? e0 : 0.2f * e0;
        e1 = e1 > 0.f ? e1 : 0.2f * e1;
        e2 = e2 > 0.f ? e2 : 0.2f * e2;
        e3 = e3 > 0.f ? e3 : 0.2f * e3;
        online_upd(m, d, acc, e0, x0);
        online_upd(m, d, acc, e1, x1);
        online_upd(m, d, acc, e2, x2);
        online_upd(m, d, acc, e3, x3);
    }
    for (; j < deg; j++) {
        unsigned s = (unsigned)__ldg(&g_csr[base + j]);
        float e = ALS[s * NHEAD + hl] + ac;
        float4 xv = XH[s * 32u + (unsigned)l];
        e = e > 0.f ? e : 0.2f * e;
        online_upd(m, d, acc, e, xv);
    }

    float inv = 1.f / (d + 1e-16f);
    acc.x *= inv; acc.y *= inv; acc.z *= inv; acc.w *= inv;

    const float4 b = ((const float4*)bias)[l];
    acc.x += b.x; acc.y += b.y; acc.z += b.z; acc.w += b.w;
    if (do_elu) {
        acc.x = acc.x > 0.f ? acc.x : expm1f(acc.x);
        acc.y = acc.y > 0.f ? acc.y : expm1f(acc.y);
        acc.z = acc.z > 0.f ? acc.z : expm1f(acc.z);
        acc.w = acc.w > 0.f ? acc.w : expm1f(acc.w);
    }
    OUT[(unsigned)n * 32u + (unsigned)l] = acc;
}

// ---------------- launch ----------------
extern "C" void kernel_launch(void* const* d_in, const int* in_sizes, int n_in,
                              void* d_out, int out_size) {
    const float* x   = (const float*)d_in[0];
    const void*  ei  = d_in[1];
    const float* W1  = (const float*)d_in[2];
    const float* as1 = (const float*)d_in[3];
    const float* ad1 = (const float*)d_in[4];
    const float* b1  = (const float*)d_in[5];
    const float* W2  = (const float*)d_in[6];
    const float* as2 = (const float*)d_in[7];
    const float* ad2 = (const float*)d_in[8];
    const float* b2  = (const float*)d_in[9];

    int N = in_sizes[0] / HID;
    int E = in_sizes[1] / 2;
    int ET = E + N;

    const size_t smem = (16384 + 8192 + 256) * sizeof(float);  // 99328 B
    cudaFuncSetAttribute(k_gemm, cudaFuncAttributeMaxDynamicSharedMemorySize, (int)smem);

    void *p_xh, *p_h, *p_als, *p_ald;
    cudaGetSymbolAddress(&p_xh, g_xh);
    cudaGetSymbolAddress(&p_h,  g_h);
    cudaGetSymbolAddress(&p_als, g_als);
    cudaGetSymbolAddress(&p_ald, g_ald);
    float4* xh4 = (float4*)p_xh;
    float4* h4  = (float4*)p_h;
    float*  als = (float*)p_als;
    float*  ald = (float*)p_ald;

    // CSR build (shared by both layers)
    k_init<<<(N + 256) / 256, 256>>>((const unsigned*)ei, N);
    k_count<<<(ET + 255) / 256, 256>>>(ei, E, N);
    k_scan<<<1, 1024>>>(N);
    k_scatter<<<(ET + 255) / 256, 256>>>(ei, E, N);

    int gemm_blocks = (N + 63) / 64;
    int agg_blocks = (N + 15) / 16;  // 16 warps per block

    // layer 1
    k_gemm<<<gemm_blocks, 256, smem>>>((const float4*)x, W1, as1, ad1, xh4, als, ald, N);
    k_agg<<<agg_blocks, 512>>>(xh4, als, ald, b1, h4, N, 1);

    // layer 2
    k_gemm<<<gemm_blocks, 256, smem>>>((const float4*)h4, W2, as2, ad2, xh4, als, ald, N);
    k_agg<<<agg_blocks, 512>>>(xh4, als, ald, b2, (float4*)d_out, N, 0);
}